// round 1
// baseline (speedup 1.0000x reference)
#include <cuda_runtime.h>

// Problem: B=4, H=8, S=2048, D=8
//   q = x @ Wq^T + bq ; k = x @ Wk^T + bk
//   scores = (q . k) / sqrt(8) + mask * (-10000)   (mask broadcast over heads)
//   out = softmax(scores) @ x
//
// Strategy (Round 1, fp32 FMA-bound baseline):
//   CTA = (batch, head, q-tile of 256 queries); lane == one query.
//   k[2048][8] precomputed into SMEM once per CTA.
//   Warp iterates keys: k-vec & v-vec reads are uniform (broadcast -> cheap),
//   mask tile staged transposed in SMEM (per-lane conflict-free).
//   Online softmax, log2e folded into q-scale & mask constant -> 1 EX2/key.

#define S_LEN    2048
#define D_DIM    8
#define TQ       256       // queries per CTA == threads
#define TK       32        // key tile staged in smem (mask)
#define NTHREADS 256

__device__ __forceinline__ float ex2_approx(float x) {
    float r;
    asm("ex2.approx.ftz.f32 %0, %1;" : "=f"(r) : "f"(x));
    return r;
}

__global__ __launch_bounds__(NTHREADS, 2)
void attn_fp32_kernel(const float* __restrict__ x,     // [B,H,S,D]
                      const float* __restrict__ mask,  // [B,1,S,S]
                      const float* __restrict__ Wq,    // [D,D]
                      const float* __restrict__ bq,    // [D]
                      const float* __restrict__ Wk,    // [D,D]
                      const float* __restrict__ bk,    // [D]
                      float* __restrict__ out)         // [B,H,S,D]
{
    extern __shared__ float smem[];
    float* ks    = smem;                    // [S_LEN * D]  = 16384 floats
    float* maskT = ks + S_LEN * D_DIM;      // [TK * TQ]    =  8192 floats
    float* wq_s  = maskT + TK * TQ;         // 64
    float* bq_s  = wq_s + 64;               // 8
    float* wk_s  = bq_s + 8;                // 64
    float* bk_s  = wk_s + 64;               // 8

    const int t  = threadIdx.x;
    const int qt = blockIdx.x;
    const int h  = blockIdx.y;
    const int b  = blockIdx.z;

    const float* xb = x + ((size_t)(b * 8 + h) * S_LEN) * D_DIM;  // [S, D]
    const float* mb = mask + (size_t)b * S_LEN * S_LEN;           // [S, S]
    const int qbase = qt * TQ;

    if (t < 64) { wq_s[t] = Wq[t]; wk_s[t] = Wk[t]; }
    if (t < 8)  { bq_s[t] = bq[t]; bk_s[t] = bk[t]; }
    __syncthreads();

    // ---- precompute k for all 2048 keys into smem ----
    for (int key = t; key < S_LEN; key += NTHREADS) {
        const float4* xr = (const float4*)(xb + key * D_DIM);
        float4 a0 = xr[0], a1 = xr[1];
        float xv[D_DIM] = {a0.x, a0.y, a0.z, a0.w, a1.x, a1.y, a1.z, a1.w};
        #pragma unroll
        for (int d = 0; d < D_DIM; d++) {
            float acc = bk_s[d];
            #pragma unroll
            for (int e = 0; e < D_DIM; e++)
                acc = fmaf(xv[e], wk_s[d * D_DIM + e], acc);
            ks[key * D_DIM + d] = acc;
        }
    }

    // ---- q for my query (scale & log2e folded in) ----
    const float LOG2E = 1.4426950408889634f;
    const float QS    = LOG2E * 0.35355339059327373f;   // log2e / sqrt(8)
    const float MC    = -10000.0f * LOG2E;

    float q[D_DIM];
    {
        const float4* xr = (const float4*)(xb + (size_t)(qbase + t) * D_DIM);
        float4 a0 = xr[0], a1 = xr[1];
        float xv[D_DIM] = {a0.x, a0.y, a0.z, a0.w, a1.x, a1.y, a1.z, a1.w};
        #pragma unroll
        for (int d = 0; d < D_DIM; d++) {
            float acc = bq_s[d];
            #pragma unroll
            for (int e = 0; e < D_DIM; e++)
                acc = fmaf(xv[e], wq_s[d * D_DIM + e], acc);
            q[d] = acc * QS;
        }
    }

    // ---- online softmax over all keys ----
    float m = -1e30f, l = 0.0f;
    float acc0 = 0.f, acc1 = 0.f, acc2 = 0.f, acc3 = 0.f;
    float acc4 = 0.f, acc5 = 0.f, acc6 = 0.f, acc7 = 0.f;

    const float* mrow = mb + (size_t)(qbase + t) * S_LEN;

    for (int tile = 0; tile < S_LEN / TK; tile++) {
        __syncthreads();  // previous tile's maskT fully consumed
        // stage mask tile transposed: maskT[kk][query]
        const float4* mr = (const float4*)(mrow + tile * TK);
        #pragma unroll
        for (int j = 0; j < TK / 4; j++) {
            float4 mv = mr[j];
            maskT[(4 * j + 0) * TQ + t] = mv.x;
            maskT[(4 * j + 1) * TQ + t] = mv.y;
            maskT[(4 * j + 2) * TQ + t] = mv.z;
            maskT[(4 * j + 3) * TQ + t] = mv.w;
        }
        __syncthreads();

        const int kb = tile * TK;
        #pragma unroll 4
        for (int kk = 0; kk < TK; kk++) {
            const int key = kb + kk;
            const float4* kr = (const float4*)(ks + key * D_DIM);
            float4 k0 = kr[0], k1 = kr[1];                        // LDS broadcast
            const float4* vr = (const float4*)(xb + key * D_DIM); // LDG broadcast (L1)
            float4 v0 = vr[0], v1 = vr[1];

            float s = maskT[kk * TQ + t] * MC;
            s = fmaf(q[0], k0.x, s);
            s = fmaf(q[1], k0.y, s);
            s = fmaf(q[2], k0.z, s);
            s = fmaf(q[3], k0.w, s);
            s = fmaf(q[4], k1.x, s);
            s = fmaf(q[5], k1.y, s);
            s = fmaf(q[6], k1.z, s);
            s = fmaf(q[7], k1.w, s);

            if (s > m) {   // rare after warmup (~8 per 2048 keys per lane)
                float c = ex2_approx(m - s);
                l *= c;
                acc0 *= c; acc1 *= c; acc2 *= c; acc3 *= c;
                acc4 *= c; acc5 *= c; acc6 *= c; acc7 *= c;
                m = s;
            }
            float p = ex2_approx(s - m);
            l += p;
            acc0 = fmaf(p, v0.x, acc0);
            acc1 = fmaf(p, v0.y, acc1);
            acc2 = fmaf(p, v0.z, acc2);
            acc3 = fmaf(p, v0.w, acc3);
            acc4 = fmaf(p, v1.x, acc4);
            acc5 = fmaf(p, v1.y, acc5);
            acc6 = fmaf(p, v1.z, acc6);
            acc7 = fmaf(p, v1.w, acc7);
        }
    }

    const float inv = 1.0f / l;
    float4* orow = (float4*)(out + ((size_t)(b * 8 + h) * S_LEN + qbase + t) * D_DIM);
    orow[0] = make_float4(acc0 * inv, acc1 * inv, acc2 * inv, acc3 * inv);
    orow[1] = make_float4(acc4 * inv, acc5 * inv, acc6 * inv, acc7 * inv);
}

extern "C" void kernel_launch(void* const* d_in, const int* in_sizes, int n_in,
                              void* d_out, int out_size) {
    const float* x    = (const float*)d_in[0];
    const float* mask = (const float*)d_in[1];
    const float* Wq   = (const float*)d_in[2];
    const float* bq   = (const float*)d_in[3];
    const float* Wk   = (const float*)d_in[4];
    const float* bk   = (const float*)d_in[5];
    float* out = (float*)d_out;

    const int smem_bytes = (S_LEN * D_DIM + TK * TQ + 64 + 8 + 64 + 8) * sizeof(float);

    static int attr_set = 0;  // setting an attribute is idempotent & deterministic
    if (!attr_set) {
        cudaFuncSetAttribute(attn_fp32_kernel,
                             cudaFuncAttributeMaxDynamicSharedMemorySize, smem_bytes);
        attr_set = 1;
    }

    dim3 grid(8, 8, 4);   // (q-tiles, heads, batch)
    dim3 block(NTHREADS);
    attn_fp32_kernel<<<grid, block, smem_bytes>>>(x, mask, Wq, bq, Wk, bk, out);
}

// round 3
// speedup vs baseline: 2.1151x; 2.1151x over previous
#include <cuda_runtime.h>
#include <cstdint>

// B=4, H=8, S=2048, D=8 fused attention.
// R3 (= R2 re-bench; infra failure last round): coalesced cp.async mask staging
// (double-buffered), QPT=2 queries/thread, packed fma.rn.f32x2 math,
// 4-key groups with amortized online-softmax max.

#define S_LEN    2048
#define D_DIM    8
#define NTHREADS 128
#define TQ       256          // queries per CTA (2 per thread)
#define TK       16           // keys per mask tile
#define MSTRIDE  20           // TK + 4 pad floats: 80B row stride (16B aligned, conflict-free)
#define NTILES   (S_LEN / TK) // 128

typedef unsigned long long u64;

__device__ __forceinline__ float ex2f(float x) {
    float r; asm("ex2.approx.ftz.f32 %0, %1;" : "=f"(r) : "f"(x)); return r;
}
__device__ __forceinline__ u64 fma2(u64 a, u64 b, u64 c) {
    u64 r; asm("fma.rn.f32x2 %0, %1, %2, %3;" : "=l"(r) : "l"(a), "l"(b), "l"(c)); return r;
}
__device__ __forceinline__ u64 mul2(u64 a, u64 b) {
    u64 r; asm("mul.rn.f32x2 %0, %1, %2;" : "=l"(r) : "l"(a), "l"(b)); return r;
}
__device__ __forceinline__ u64 pk2(float lo, float hi) {
    u64 r; asm("mov.b64 %0, {%1, %2};" : "=l"(r) : "f"(lo), "f"(hi)); return r;
}
__device__ __forceinline__ void up2(u64 v, float& lo, float& hi) {
    asm("mov.b64 {%0, %1}, %2;" : "=f"(lo), "=f"(hi) : "l"(v));
}
__device__ __forceinline__ uint32_t s2u(const void* p) {
    uint32_t a;
    asm("{ .reg .u64 t; cvta.to.shared.u64 t, %1; cvt.u32.u64 %0, t; }" : "=r"(a) : "l"(p));
    return a;
}
__device__ __forceinline__ void cp16(uint32_t dst, const void* src) {
    asm volatile("cp.async.cg.shared.global [%0], [%1], 16;" :: "r"(dst), "l"(src));
}
__device__ __forceinline__ void cpcommit() { asm volatile("cp.async.commit_group;"); }
__device__ __forceinline__ void cpwait0() { asm volatile("cp.async.wait_group 0;"); }

__global__ __launch_bounds__(NTHREADS, 2)
void attn_r3_kernel(const float* __restrict__ x,     // [B,H,S,D]
                    const float* __restrict__ mask,  // [B,1,S,S]
                    const float* __restrict__ Wq,    // [D,D]
                    const float* __restrict__ bq,    // [D]
                    const float* __restrict__ Wk,    // [D,D]
                    const float* __restrict__ bk,    // [D]
                    float* __restrict__ out)         // [B,H,S,D]
{
    extern __shared__ float smem[];
    float* ks   = smem;                         // [S_LEN * D_DIM] = 16384 floats
    float* mk   = ks + S_LEN * D_DIM;           // [2 * TQ * MSTRIDE] = 10240 floats
    float* wq_s = mk + 2 * TQ * MSTRIDE;        // 64
    float* bq_s = wq_s + 64;                    // 8
    float* wk_s = bq_s + 8;                     // 64
    float* bk_s = wk_s + 64;                    // 8

    const int t  = threadIdx.x;
    const int qt = blockIdx.x;
    const int h  = blockIdx.y;
    const int b  = blockIdx.z;

    const float* xb = x + ((size_t)(b * 8 + h) * S_LEN) * D_DIM;  // [S, D]
    const float* mb = mask + (size_t)b * S_LEN * S_LEN;           // [S, S]
    const int qbase = qt * TQ;

    if (t < 64) { wq_s[t] = Wq[t]; wk_s[t] = Wk[t]; }
    if (t < 8)  { bq_s[t] = bq[t]; bk_s[t] = bk[t]; }
    __syncthreads();

    const uint32_t mk_u32 = s2u(mk);

    // ---- prefetch mask tile 0 (overlaps with k precompute) ----
    // tile layout: mk[buf*TQ*MSTRIDE + row*MSTRIDE + col], row = local query
    {
        #pragma unroll
        for (int i = 0; i < 8; i++) {
            int idx = t + i * NTHREADS;           // 0..1023
            int row = idx >> 2;
            int c4  = idx & 3;
            cp16(mk_u32 + (uint32_t)(row * MSTRIDE + c4 * 4) * 4,
                 mb + (size_t)(qbase + row) * S_LEN + c4 * 4);
        }
        cpcommit();
    }

    // ---- precompute k for all 2048 keys into smem ----
    for (int key = t; key < S_LEN; key += NTHREADS) {
        const float4* xr = (const float4*)(xb + key * D_DIM);
        float4 a0 = xr[0], a1 = xr[1];
        float xv[D_DIM] = {a0.x, a0.y, a0.z, a0.w, a1.x, a1.y, a1.z, a1.w};
        float kv[D_DIM];
        #pragma unroll
        for (int d = 0; d < D_DIM; d++) {
            float acc = bk_s[d];
            #pragma unroll
            for (int e = 0; e < D_DIM; e++)
                acc = fmaf(xv[e], wk_s[d * D_DIM + e], acc);
            kv[d] = acc;
        }
        float4* kr = (float4*)(ks + key * D_DIM);
        kr[0] = make_float4(kv[0], kv[1], kv[2], kv[3]);
        kr[1] = make_float4(kv[4], kv[5], kv[6], kv[7]);
    }

    // ---- q for my two queries (A = qbase+t, B = qbase+t+128), packed f32x2 ----
    const float LOG2E = 1.4426950408889634f;
    const float QS    = LOG2E * 0.35355339059327373f;   // log2e / sqrt(8)
    const float MC    = -10000.0f * LOG2E;

    u64 qA[4], qB[4];
    #pragma unroll
    for (int w = 0; w < 2; w++) {
        int qi = qbase + t + w * 128;
        const float4* xr = (const float4*)(xb + (size_t)qi * D_DIM);
        float4 a0 = xr[0], a1 = xr[1];
        float xv[D_DIM] = {a0.x, a0.y, a0.z, a0.w, a1.x, a1.y, a1.z, a1.w};
        float qv[D_DIM];
        #pragma unroll
        for (int d = 0; d < D_DIM; d++) {
            float acc = bq_s[d];
            #pragma unroll
            for (int e = 0; e < D_DIM; e++)
                acc = fmaf(xv[e], wq_s[d * D_DIM + e], acc);
            qv[d] = acc * QS;
        }
        u64* qq = w ? qB : qA;
        qq[0] = pk2(qv[0], qv[1]);
        qq[1] = pk2(qv[2], qv[3]);
        qq[2] = pk2(qv[4], qv[5]);
        qq[3] = pk2(qv[6], qv[7]);
    }

    // ---- online softmax over keys ----
    float mA = -1e30f, lA = 0.0f, mB = -1e30f, lB = 0.0f;
    u64 aA0 = 0, aA1 = 0, aA2 = 0, aA3 = 0;   // f32x2 pairs of (0,0)
    u64 aB0 = 0, aB1 = 0, aB2 = 0, aB3 = 0;

    for (int tile = 0; tile < NTILES; tile++) {
        const int buf = tile & 1;
        cpwait0();            // tile's mask data landed (own copies)
        __syncthreads();      // all copies visible; all done with compute(tile-1)

        // prefetch next tile into other buffer
        if (tile + 1 < NTILES) {
            const int nbuf = buf ^ 1;
            const int nkb  = (tile + 1) * TK;
            #pragma unroll
            for (int i = 0; i < 8; i++) {
                int idx = t + i * NTHREADS;
                int row = idx >> 2;
                int c4  = idx & 3;
                cp16(mk_u32 + (uint32_t)((nbuf * TQ + row) * MSTRIDE + c4 * 4) * 4,
                     mb + (size_t)(qbase + row) * S_LEN + nkb + c4 * 4);
            }
            cpcommit();
        }

        const int kb = tile * TK;
        const float* mrowA = mk + (buf * TQ + t) * MSTRIDE;
        const float* mrowB = mrowA + 128 * MSTRIDE;

        #pragma unroll
        for (int g = 0; g < TK / 4; g++) {
            float4 mA4 = *(const float4*)(mrowA + g * 4);
            float4 mB4 = *(const float4*)(mrowB + g * 4);
            const float* mAp = (const float*)&mA4;
            const float* mBp = (const float*)&mB4;

            float sA[4], sB[4];
            u64 v0a[4], v1a[4], v2a[4], v3a[4];

            #pragma unroll
            for (int j = 0; j < 4; j++) {
                const int key = kb + g * 4 + j;
                ulonglong2 k0 = *(const ulonglong2*)(ks + key * D_DIM);      // (k0,k1),(k2,k3)
                ulonglong2 k1 = *(const ulonglong2*)(ks + key * D_DIM + 4);  // (k4,k5),(k6,k7)
                ulonglong2 v0 = *(const ulonglong2*)(xb + key * D_DIM);      // broadcast LDG (L1)
                ulonglong2 v1 = *(const ulonglong2*)(xb + key * D_DIM + 4);
                v0a[j] = v0.x; v1a[j] = v0.y; v2a[j] = v1.x; v3a[j] = v1.y;

                u64 pa = mul2(qA[0], k0.x);
                pa = fma2(qA[1], k0.y, pa);
                pa = fma2(qA[2], k1.x, pa);
                pa = fma2(qA[3], k1.y, pa);
                float al, ah; up2(pa, al, ah);
                sA[j] = fmaf(mAp[j], MC, al + ah);

                u64 pb = mul2(qB[0], k0.x);
                pb = fma2(qB[1], k0.y, pb);
                pb = fma2(qB[2], k1.x, pb);
                pb = fma2(qB[3], k1.y, pb);
                float bl, bh; up2(pb, bl, bh);
                sB[j] = fmaf(mBp[j], MC, bl + bh);
            }

            float gA = fmaxf(fmaxf(sA[0], sA[1]), fmaxf(sA[2], sA[3]));
            if (__builtin_expect(gA > mA, 0)) {
                float c = ex2f(mA - gA); mA = gA; lA *= c;
                u64 c2 = pk2(c, c);
                aA0 = mul2(aA0, c2); aA1 = mul2(aA1, c2);
                aA2 = mul2(aA2, c2); aA3 = mul2(aA3, c2);
            }
            float gB = fmaxf(fmaxf(sB[0], sB[1]), fmaxf(sB[2], sB[3]));
            if (__builtin_expect(gB > mB, 0)) {
                float c = ex2f(mB - gB); mB = gB; lB *= c;
                u64 c2 = pk2(c, c);
                aB0 = mul2(aB0, c2); aB1 = mul2(aB1, c2);
                aB2 = mul2(aB2, c2); aB3 = mul2(aB3, c2);
            }

            #pragma unroll
            for (int j = 0; j < 4; j++) {
                float pA = ex2f(sA[j] - mA); lA += pA;
                u64 pA2 = pk2(pA, pA);
                aA0 = fma2(pA2, v0a[j], aA0);
                aA1 = fma2(pA2, v1a[j], aA1);
                aA2 = fma2(pA2, v2a[j], aA2);
                aA3 = fma2(pA2, v3a[j], aA3);

                float pB = ex2f(sB[j] - mB); lB += pB;
                u64 pB2 = pk2(pB, pB);
                aB0 = fma2(pB2, v0a[j], aB0);
                aB1 = fma2(pB2, v1a[j], aB1);
                aB2 = fma2(pB2, v2a[j], aB2);
                aB3 = fma2(pB2, v3a[j], aB3);
            }
        }
    }

    // ---- epilogue ----
    const size_t obase = (size_t)(b * 8 + h) * S_LEN;
    {
        float inv = 1.0f / lA;
        float o[8];
        up2(aA0, o[0], o[1]); up2(aA1, o[2], o[3]);
        up2(aA2, o[4], o[5]); up2(aA3, o[6], o[7]);
        float4* orow = (float4*)(out + (obase + qbase + t) * D_DIM);
        orow[0] = make_float4(o[0] * inv, o[1] * inv, o[2] * inv, o[3] * inv);
        orow[1] = make_float4(o[4] * inv, o[5] * inv, o[6] * inv, o[7] * inv);
    }
    {
        float inv = 1.0f / lB;
        float o[8];
        up2(aB0, o[0], o[1]); up2(aB1, o[2], o[3]);
        up2(aB2, o[4], o[5]); up2(aB3, o[6], o[7]);
        float4* orow = (float4*)(out + (obase + qbase + t + 128) * D_DIM);
        orow[0] = make_float4(o[0] * inv, o[1] * inv, o[2] * inv, o[3] * inv);
        orow[1] = make_float4(o[4] * inv, o[5] * inv, o[6] * inv, o[7] * inv);
    }
}

extern "C" void kernel_launch(void* const* d_in, const int* in_sizes, int n_in,
                              void* d_out, int out_size) {
    const float* x    = (const float*)d_in[0];
    const float* mask = (const float*)d_in[1];
    const float* Wq   = (const float*)d_in[2];
    const float* bq   = (const float*)d_in[3];
    const float* Wk   = (const float*)d_in[4];
    const float* bk   = (const float*)d_in[5];
    float* out = (float*)d_out;

    const int smem_bytes = (S_LEN * D_DIM + 2 * TQ * MSTRIDE + 64 + 8 + 64 + 8) * sizeof(float);

    cudaFuncSetAttribute(attn_r3_kernel,
                         cudaFuncAttributeMaxDynamicSharedMemorySize, smem_bytes);

    dim3 grid(S_LEN / TQ, 8, 4);   // (8 q-tiles, 8 heads, 4 batch) = 256 CTAs
    dim3 block(NTHREADS);
    attn_r3_kernel<<<grid, block, smem_bytes>>>(x, mask, Wq, bq, Wk, bk, out);
}